// round 12
// baseline (speedup 1.0000x reference)
#include <cuda_runtime.h>
#include <cstdint>

// SKA: out[n, g*8+c, h, w] = sum_{7x7} x_pad[n, g*8+c, h+i, w+j] * w[n, c, i*7+j, h, w]
// x [8,512,96,96] f32, w [8,8,49,96,96] f32, out [8,512,96,96] f32.
//
// R12 = R11 winner (cooperative lane-pair quad; 49 weight pairs = 98 regs per
// thread; 64 B LDS per output; scalar odd taps; shfl.bfly(1) merge; PITCH=112;
// 2 buffers x 4-channel slabs, barrier per 4 channels) + ONE change:
// g-SPLIT x4 against wave quantization. 1536 CTAs over 296 slots = 5.19 waves
// -> makespan 6 waves (15.6% idle tail). Each tile's 64 channels now split
// into 4 CTAs x 16 channels: 6144 CTAs = 20.75 waves -> 21 (1.2% tail).
// g indexes independent OUTPUT channels (no reduction), so the split is exact.
// Sibling CTAs (same tile, different g-range) are adjacent in blockIdx.x so
// they co-schedule and their repeated weight reads hit L2.

#define N_    8
#define IC    512
#define H_    96
#define W_    96
#define WC    8
#define G_    64
#define PAD   3
#define HT    4                     // output rows per CTA (2 row-groups x 2)
#define NTHR  192
#define TROWS (HT + 2 * PAD)        // 10 staged rows
#define PITCH 112                   // 3 zero | 96 data | zeros; 112%32==16
#define TILE_F (TROWS * PITCH)      // 1120 floats per channel slab
#define HW    (H_ * W_)             // 9216
#define CSTR  ((size_t)WC * HW)     // x/out channel stride between g steps
#define CPB   4                     // channels per pipeline block
#define GSPLIT 4                    // CTAs per tile along g
#define GPC   (G_ / GSPLIT)         // 16 channels per CTA
#define NBLK  (GPC / CPB)           // 4 pipeline blocks
#define ELPT  ((TROWS * W_) / NTHR) // 5 staged elements per thread per channel

typedef unsigned long long u64;

static __device__ __forceinline__ void ffma2(u64& d, u64 a, u64 b) {
    asm("fma.rn.f32x2 %0, %1, %2, %0;" : "+l"(d) : "l"(a), "l"(b));
}
static __device__ __forceinline__ u64 fadd2(u64 a, u64 b) {
    u64 d; asm("add.rn.f32x2 %0, %1, %2;" : "=l"(d) : "l"(a), "l"(b)); return d;
}
// lo += xl*w.lo, hi += xh*w.hi; splitting the weight pair is register aliasing.
static __device__ __forceinline__ void odd_tap(float& lo, float& hi,
                                               float xl, float xh, u64 w) {
    asm("{\n\t"
        ".reg .f32 wl, wh;\n\t"
        "mov.b64 {wl, wh}, %4;\n\t"
        "fma.rn.f32 %0, %2, wl, %0;\n\t"
        "fma.rn.f32 %1, %3, wh, %1;\n\t"
        "}" : "+f"(lo), "+f"(hi) : "f"(xl), "f"(xh), "l"(w));
}
static __device__ __forceinline__ void unpack2(u64 v, float& a, float& b) {
    asm("mov.b64 {%0, %1}, %2;" : "=f"(a), "=f"(b) : "l"(v));
}
static __device__ __forceinline__ u64 pack2(float a, float b) {
    u64 r; asm("mov.b64 %0, {%1, %2};" : "=l"(r) : "f"(a), "f"(b)); return r;
}
static __device__ __forceinline__ u64 shfl_x1(u64 v) {
    uint32_t lo = (uint32_t)v, hi = (uint32_t)(v >> 32);
    lo = __shfl_xor_sync(0xffffffffu, lo, 1);
    hi = __shfl_xor_sync(0xffffffffu, hi, 1);
    return ((u64)hi << 32) | lo;
}
static __device__ __forceinline__ void cp4(uint32_t s, const float* g, int sz) {
    asm volatile("cp.async.ca.shared.global [%0], [%1], 4, %2;"
                 :: "r"(s), "l"(g), "r"(sz));
}

// 7 taps of one kernel row into one chain set (even pairs + odd scalars).
#define TAP7(E, LO, HI, WA)                          \
    do {                                             \
        ffma2(E, U0, (WA)[0]);                       \
        ffma2(E, U1, (WA)[2]);                       \
        ffma2(E, U2, (WA)[4]);                       \
        ffma2(E, U3, (WA)[6]);                       \
        odd_tap(LO, HI, f1, f2, (WA)[1]);            \
        odd_tap(LO, HI, f3, f4, (WA)[3]);            \
        odd_tap(LO, HI, f5, f6, (WA)[5]);            \
    } while (0)

__global__ __launch_bounds__(NTHR, 2)
void ska_kernel(const float* __restrict__ x, const float* __restrict__ wgt,
                float* __restrict__ out) {
    __shared__ float smem[8 * TILE_F];   // 2 buffers x 4 channel slabs = 35.8 KB

    const int tid  = threadIdx.x;
    const int gs   = blockIdx.x % GSPLIT;   // g-range: fastest-varying -> L2 share
    const int ht   = blockIdx.x / GSPLIT;   // 0..23
    const int c    = blockIdx.y;            // 0..7
    const int n    = blockIdx.z;            // 0..7
    const int h0   = ht * HT;
    const int role = tid & 1;            // 0 = A (rows 0..3), 1 = B (rows 7..4)
    const int pid  = tid >> 1;           // 0..95
    const int rg   = pid / 48;           // row-group: output rows 2rg, 2rg+1
    const int cp   = pid % 48;
    const int w0   = 2 * cp;

    // Zero left/right halo columns of all 8 slabs (reads touch floats 0..101).
    for (int z = tid; z < 8 * TROWS * 8; z += NTHR) {
        int b = z / (TROWS * 8), rem = z % (TROWS * 8);
        int row = rem / 8, ci = rem % 8;
        int col = (ci < 3) ? ci : 99 + (ci - 3);
        smem[b * TILE_F + row * PITCH + col] = 0.0f;
    }

    // Weight register cache: exactly 49 pairs per thread (98 regs).
    // own = pixel this role stores (A: row 2rg; B: row 2rg+1).
    // A: light = own i=0;  heavy m=0..2: own i=m+1, other i=m.
    // B: light = own i=6;  heavy m=0..2: own i=5-m, other i=6-m.
    const float* W0b = wgt + ((size_t)(n * WC + c) * 49) * HW
                           + (size_t)(h0 + 2 * rg) * W_ + w0;
    const float* ownB = role ? (W0b + W_) : W0b;
    const float* othB = role ? W0b : (W0b + W_);
    u64 WL[7], WHo[3][7], WHx[3][7];
    {
        const int liRow = role ? 6 : 0;
        #pragma unroll
        for (int j = 0; j < 7; j++)
            WL[j] = *(const u64*)(ownB + (size_t)(liRow * 7 + j) * HW);
        #pragma unroll
        for (int m = 0; m < 3; m++) {
            const int ro = role ? (5 - m) : (m + 1);
            const int rx = role ? (6 - m) : m;
            #pragma unroll
            for (int j = 0; j < 7; j++) {
                WHo[m][j] = *(const u64*)(ownB + (size_t)(ro * 7 + j) * HW);
                WHx[m][j] = *(const u64*)(othB + (size_t)(rx * 7 + j) * HW);
            }
        }
    }

    // Staging descriptors: 10 rows x 96 cols, ELPT=5 elements/thread/channel.
    // Base channel for this CTA: c + 8 * (gs * GPC).
    const float* xc = x + (size_t)n * IC * HW + (size_t)c * HW
                        + (size_t)(gs * GPC) * CSTR;
    const uint32_t sbase = (uint32_t)__cvta_generic_to_shared(smem);
    uint32_t soff[ELPT];
    int      gofs[ELPT];
    int      gsz[ELPT];
    #pragma unroll
    for (int k = 0; k < ELPT; k++) {
        int idx = tid + k * NTHR;            // 0..959
        int row = idx / W_, col = idx - row * W_;
        int hr  = h0 - PAD + row;
        gsz[k]  = (hr >= 0 && hr < H_) ? 4 : 0;
        int hrc = hr < 0 ? 0 : (hr >= H_ ? H_ - 1 : hr);
        soff[k] = (uint32_t)(row * PITCH + 3 + col) * 4u;
        gofs[k] = hrc * W_ + col;
    }
    // Stage block b = local channels 4b..4b+3 into buffer b&1; one commit group.
    auto stage = [&](int b) {
        #pragma unroll
        for (int cc = 0; cc < CPB; cc++) {
            uint32_t sb = sbase + (uint32_t)(((b & 1) * CPB + cc) * TILE_F) * 4u;
            const float* base = xc + (size_t)(CPB * b + cc) * CSTR;
            #pragma unroll
            for (int k = 0; k < ELPT; k++)
                cp4(sb + soff[k], base + gofs[k], gsz[k]);
        }
        asm volatile("cp.async.commit_group;");
    };

    stage(0);

    // Per-thread tile-row float offsets: A row kk, B row 7-kk (plus row-group).
    int rowF[4];
    #pragma unroll
    for (int kk = 0; kk < 4; kk++)
        rowF[kk] = (2 * rg + (role ? (7 - kk) : kk)) * PITCH + w0;

    float* op = out + (size_t)n * IC * HW + (size_t)c * HW
                    + (size_t)(gs * GPC) * CSTR
                    + (size_t)(h0 + 2 * rg + role) * W_ + w0;

    for (int b = 0; b < NBLK; ++b) {
        // Block b's group was issued one full compute block ago (except b=0):
        // wait_group 0 is cheap. Barrier publishes all slab writes AND proves
        // everyone finished computing block b-1, so buffer (b+1)&1 = (b-1)&1
        // is safe to overwrite below.
        asm volatile("cp.async.wait_group 0;");
        __syncthreads();
        if (b + 1 < NBLK) stage(b + 1);

        const float* bufB = smem + (b & 1) * CPB * TILE_F;
        #pragma unroll
        for (int gg = 0; gg < CPB; gg++) {
            const float* tb = bufB + gg * TILE_F;
            u64 eO = 0ull, eX = 0ull;               // even-tap chains
            float oLo = 0.f, oHi = 0.f, xLo = 0.f, xHi = 0.f;  // odd scalars
            // Light row (kk=0): 7 taps into the own-pixel chains.
            {
                const u64* rp = (const u64*)(tb + rowF[0]);  // 8B aligned
                u64 U0 = rp[0], U1 = rp[1], U2 = rp[2], U3 = rp[3];
                float f0, f1, f2, f3, f4, f5, f6, f7;
                unpack2(U0, f0, f1); unpack2(U1, f2, f3);
                unpack2(U2, f4, f5); unpack2(U3, f6, f7);
                TAP7(eO, oLo, oHi, WL);
            }
            // Heavy rows (kk=1..3): 7 taps own + 7 taps other.
            #pragma unroll
            for (int kk = 1; kk < 4; kk++) {
                const u64* rp = (const u64*)(tb + rowF[kk]);
                u64 U0 = rp[0], U1 = rp[1], U2 = rp[2], U3 = rp[3];
                float f0, f1, f2, f3, f4, f5, f6, f7;
                unpack2(U0, f0, f1); unpack2(U1, f2, f3);
                unpack2(U2, f4, f5); unpack2(U3, f6, f7);
                TAP7(eO, oLo, oHi, WHo[kk - 1]);
                TAP7(eX, xLo, xHi, WHx[kk - 1]);
            }
            // Fold, swap the other-pixel partial with the partner lane, store.
            u64 ownF = fadd2(eO, pack2(oLo, oHi));
            u64 othF = fadd2(eX, pack2(xLo, xHi));
            u64 recv = shfl_x1(othF);   // partner's partial for MY pixel
            *(u64*)op = fadd2(ownF, recv);
            op += CSTR;
        }
    }
}

extern "C" void kernel_launch(void* const* d_in, const int* in_sizes, int n_in,
                              void* d_out, int out_size) {
    const float* x = (const float*)d_in[0];
    const float* w = (const float*)d_in[1];
    // x (37,748,736 elems) > w (28,901,376); guard against input ordering.
    if (n_in >= 2 && in_sizes[0] < in_sizes[1]) {
        const float* t = x; x = w; w = t;
    }
    float* out = (float*)d_out;
    dim3 grid(GSPLIT * (H_ / HT), WC, N_);   // (96, 8, 8) = 6144 CTAs, 2/SM
    ska_kernel<<<grid, NTHR>>>(x, w, out);
}

// round 13
// speedup vs baseline: 1.1330x; 1.1330x over previous
#include <cuda_runtime.h>
#include <cstdint>

// SKA: out[n, g*8+c, h, w] = sum_{7x7} x_pad[n, g*8+c, h+i, w+j] * w[n, c, i*7+j, h, w]
// x [8,512,96,96] f32, w [8,8,49,96,96] f32, out [8,512,96,96] f32.
//
// R13 = R11 winner body EXACTLY (cooperative lane-pair quad: lanes (2t,2t+1) =
// roles (A,B) share a 2x2 output quad; A reads tile rows 0..3, B rows 7..4;
// 49 weight pairs = 98 regs/thread; 64 B LDS per output; scalar odd taps;
// shfl.bfly(1) merge; PITCH=112; 2 buffers x 4-channel slabs, barrier per 4
// channels) + ONE change: TAIL-ONLY g-split against wave quantization.
// 1536 equal CTAs / 296 slots = 5.19 -> 56 slots run a 6th full CTA while 240
// idle (13.5% tail). R12 proved uniform splitting loses: per-CTA fixed cost
// P ~= 2us (weight-cache fill + pipeline fill) multiplies. Instead: tiles
// 0..1479 stay FULL 64-g CTAs (exactly 5 x 296, balanced), tiles 1480..1535
// split into 4 CTAs x 16 g (224 short CTAs at the END of grid order -> one
// short tail wave backfilled by the work-stealing scheduler).
// Model: 5*(C+P) + (C/4+P) ~= 130us vs 6*(C+P) = 147.5us.

#define N_    8
#define IC    512
#define H_    96
#define W_    96
#define WC    8
#define G_    64
#define PAD   3
#define HT    4                     // output rows per CTA (2 row-groups x 2)
#define NTHR  192
#define TROWS (HT + 2 * PAD)        // 10 staged rows
#define PITCH 112                   // 3 zero | 96 data | zeros; 112%32==16
#define TILE_F (TROWS * PITCH)      // 1120 floats per channel slab
#define HW    (H_ * W_)             // 9216
#define CSTR  ((size_t)WC * HW)     // x/out channel stride between g steps
#define CPB   4                     // channels per pipeline block
#define ELPT  ((TROWS * W_) / NTHR) // 5 staged elements per thread per channel

#define NTILE 1536                  // 24 ht x 8 c x 8 n
#define FULLT 1480                  // full-64g tiles (= 5 * 296 slots exactly)
#define SPLITK 4                    // tail tiles split into 4 CTAs x 16 g
#define GRIDX (FULLT + (NTILE - FULLT) * SPLITK)   // 1480 + 224 = 1704

typedef unsigned long long u64;

static __device__ __forceinline__ void ffma2(u64& d, u64 a, u64 b) {
    asm("fma.rn.f32x2 %0, %1, %2, %0;" : "+l"(d) : "l"(a), "l"(b));
}
static __device__ __forceinline__ u64 fadd2(u64 a, u64 b) {
    u64 d; asm("add.rn.f32x2 %0, %1, %2;" : "=l"(d) : "l"(a), "l"(b)); return d;
}
// lo += xl*w.lo, hi += xh*w.hi; splitting the weight pair is register aliasing.
static __device__ __forceinline__ void odd_tap(float& lo, float& hi,
                                               float xl, float xh, u64 w) {
    asm("{\n\t"
        ".reg .f32 wl, wh;\n\t"
        "mov.b64 {wl, wh}, %4;\n\t"
        "fma.rn.f32 %0, %2, wl, %0;\n\t"
        "fma.rn.f32 %1, %3, wh, %1;\n\t"
        "}" : "+f"(lo), "+f"(hi) : "f"(xl), "f"(xh), "l"(w));
}
static __device__ __forceinline__ void unpack2(u64 v, float& a, float& b) {
    asm("mov.b64 {%0, %1}, %2;" : "=f"(a), "=f"(b) : "l"(v));
}
static __device__ __forceinline__ u64 pack2(float a, float b) {
    u64 r; asm("mov.b64 %0, {%1, %2};" : "=l"(r) : "f"(a), "f"(b)); return r;
}
static __device__ __forceinline__ u64 shfl_x1(u64 v) {
    uint32_t lo = (uint32_t)v, hi = (uint32_t)(v >> 32);
    lo = __shfl_xor_sync(0xffffffffu, lo, 1);
    hi = __shfl_xor_sync(0xffffffffu, hi, 1);
    return ((u64)hi << 32) | lo;
}
static __device__ __forceinline__ void cp4(uint32_t s, const float* g, int sz) {
    asm volatile("cp.async.ca.shared.global [%0], [%1], 4, %2;"
                 :: "r"(s), "l"(g), "r"(sz));
}

// 7 taps of one kernel row into one chain set (even pairs + odd scalars).
#define TAP7(E, LO, HI, WA)                          \
    do {                                             \
        ffma2(E, U0, (WA)[0]);                       \
        ffma2(E, U1, (WA)[2]);                       \
        ffma2(E, U2, (WA)[4]);                       \
        ffma2(E, U3, (WA)[6]);                       \
        odd_tap(LO, HI, f1, f2, (WA)[1]);            \
        odd_tap(LO, HI, f3, f4, (WA)[3]);            \
        odd_tap(LO, HI, f5, f6, (WA)[5]);            \
    } while (0)

__global__ __launch_bounds__(NTHR, 2)
void ska_kernel(const float* __restrict__ x, const float* __restrict__ wgt,
                float* __restrict__ out) {
    __shared__ float smem[8 * TILE_F];   // 2 buffers x 4 channel slabs = 35.8 KB

    const int tid  = threadIdx.x;
    // ---- Tail-split schedule decode (uniform across the CTA) ----
    int tile, g0, nblk;
    {
        int bid = blockIdx.x;
        if (bid < FULLT) { tile = bid;                 g0 = 0;  nblk = G_ / CPB; }
        else {
            int r = bid - FULLT;                       // 0..223
            tile = FULLT + (r >> 2);                   // 4 consecutive bids/tile
            g0   = (r & 3) * (G_ / SPLITK);            // 0,16,32,48
            nblk = (G_ / SPLITK) / CPB;                // 4
        }
    }
    const int ht   = tile % 24;
    const int c    = (tile / 24) % WC;
    const int n    = tile / (24 * WC);
    const int h0   = ht * HT;
    const int role = tid & 1;            // 0 = A (rows 0..3), 1 = B (rows 7..4)
    const int pid  = tid >> 1;           // 0..95
    const int rg   = pid / 48;           // row-group: output rows 2rg, 2rg+1
    const int cp   = pid % 48;
    const int w0   = 2 * cp;

    // Zero left/right halo columns of all 8 slabs (reads touch floats 0..101).
    for (int z = tid; z < 8 * TROWS * 8; z += NTHR) {
        int b = z / (TROWS * 8), rem = z % (TROWS * 8);
        int row = rem / 8, ci = rem % 8;
        int col = (ci < 3) ? ci : 99 + (ci - 3);
        smem[b * TILE_F + row * PITCH + col] = 0.0f;
    }

    // Weight register cache: exactly 49 pairs per thread (98 regs).
    // own = pixel this role stores (A: row 2rg; B: row 2rg+1).
    // A: light = own i=0;  heavy m=0..2: own i=m+1, other i=m.
    // B: light = own i=6;  heavy m=0..2: own i=5-m, other i=6-m.
    const float* W0b = wgt + ((size_t)(n * WC + c) * 49) * HW
                           + (size_t)(h0 + 2 * rg) * W_ + w0;
    const float* ownB = role ? (W0b + W_) : W0b;
    const float* othB = role ? W0b : (W0b + W_);
    u64 WL[7], WHo[3][7], WHx[3][7];
    {
        const int liRow = role ? 6 : 0;
        #pragma unroll
        for (int j = 0; j < 7; j++)
            WL[j] = *(const u64*)(ownB + (size_t)(liRow * 7 + j) * HW);
        #pragma unroll
        for (int m = 0; m < 3; m++) {
            const int ro = role ? (5 - m) : (m + 1);
            const int rx = role ? (6 - m) : m;
            #pragma unroll
            for (int j = 0; j < 7; j++) {
                WHo[m][j] = *(const u64*)(ownB + (size_t)(ro * 7 + j) * HW);
                WHx[m][j] = *(const u64*)(othB + (size_t)(rx * 7 + j) * HW);
            }
        }
    }

    // Staging descriptors: 10 rows x 96 cols, ELPT=5 elements/thread/channel.
    const float* xc = x + (size_t)n * IC * HW + (size_t)c * HW
                        + (size_t)g0 * CSTR;     // first channel of this CTA
    const uint32_t sbase = (uint32_t)__cvta_generic_to_shared(smem);
    uint32_t soff[ELPT];
    int      gofs[ELPT];
    int      gsz[ELPT];
    #pragma unroll
    for (int k = 0; k < ELPT; k++) {
        int idx = tid + k * NTHR;            // 0..959
        int row = idx / W_, col = idx - row * W_;
        int hr  = h0 - PAD + row;
        gsz[k]  = (hr >= 0 && hr < H_) ? 4 : 0;
        int hrc = hr < 0 ? 0 : (hr >= H_ ? H_ - 1 : hr);
        soff[k] = (uint32_t)(row * PITCH + 3 + col) * 4u;
        gofs[k] = hrc * W_ + col;
    }
    // Stage block b = local channels 4b..4b+3 into buffer b&1; one commit group.
    auto stage = [&](int b) {
        #pragma unroll
        for (int cc = 0; cc < CPB; cc++) {
            uint32_t sb = sbase + (uint32_t)(((b & 1) * CPB + cc) * TILE_F) * 4u;
            const float* base = xc + (size_t)(CPB * b + cc) * CSTR;
            #pragma unroll
            for (int k = 0; k < ELPT; k++)
                cp4(sb + soff[k], base + gofs[k], gsz[k]);
        }
        asm volatile("cp.async.commit_group;");
    };

    stage(0);

    // Per-thread tile-row float offsets: A row kk, B row 7-kk (plus row-group).
    int rowF[4];
    #pragma unroll
    for (int kk = 0; kk < 4; kk++)
        rowF[kk] = (2 * rg + (role ? (7 - kk) : kk)) * PITCH + w0;

    float* op = out + (size_t)n * IC * HW + (size_t)c * HW
                    + (size_t)g0 * CSTR
                    + (size_t)(h0 + 2 * rg + role) * W_ + w0;

    for (int b = 0; b < nblk; ++b) {
        // Block b's group was issued one full compute block ago (except b=0):
        // wait_group 0 is cheap. Barrier publishes all slab writes AND proves
        // everyone finished computing block b-1, so buffer (b+1)&1 = (b-1)&1
        // is safe to overwrite below.
        asm volatile("cp.async.wait_group 0;");
        __syncthreads();
        if (b + 1 < nblk) stage(b + 1);

        const float* bufB = smem + (b & 1) * CPB * TILE_F;
        #pragma unroll
        for (int gg = 0; gg < CPB; gg++) {
            const float* tb = bufB + gg * TILE_F;
            u64 eO = 0ull, eX = 0ull;               // even-tap chains
            float oLo = 0.f, oHi = 0.f, xLo = 0.f, xHi = 0.f;  // odd scalars
            // Light row (kk=0): 7 taps into the own-pixel chains.
            {
                const u64* rp = (const u64*)(tb + rowF[0]);  // 8B aligned
                u64 U0 = rp[0], U1 = rp[1], U2 = rp[2], U3 = rp[3];
                float f0, f1, f2, f3, f4, f5, f6, f7;
                unpack2(U0, f0, f1); unpack2(U1, f2, f3);
                unpack2(U2, f4, f5); unpack2(U3, f6, f7);
                TAP7(eO, oLo, oHi, WL);
            }
            // Heavy rows (kk=1..3): 7 taps own + 7 taps other.
            #pragma unroll
            for (int kk = 1; kk < 4; kk++) {
                const u64* rp = (const u64*)(tb + rowF[kk]);
                u64 U0 = rp[0], U1 = rp[1], U2 = rp[2], U3 = rp[3];
                float f0, f1, f2, f3, f4, f5, f6, f7;
                unpack2(U0, f0, f1); unpack2(U1, f2, f3);
                unpack2(U2, f4, f5); unpack2(U3, f6, f7);
                TAP7(eO, oLo, oHi, WHo[kk - 1]);
                TAP7(eX, xLo, xHi, WHx[kk - 1]);
            }
            // Fold, swap the other-pixel partial with the partner lane, store.
            u64 ownF = fadd2(eO, pack2(oLo, oHi));
            u64 othF = fadd2(eX, pack2(xLo, xHi));
            u64 recv = shfl_x1(othF);   // partner's partial for MY pixel
            *(u64*)op = fadd2(ownF, recv);
            op += CSTR;
        }
    }
}

extern "C" void kernel_launch(void* const* d_in, const int* in_sizes, int n_in,
                              void* d_out, int out_size) {
    const float* x = (const float*)d_in[0];
    const float* w = (const float*)d_in[1];
    // x (37,748,736 elems) > w (28,901,376); guard against input ordering.
    if (n_in >= 2 && in_sizes[0] < in_sizes[1]) {
        const float* t = x; x = w; w = t;
    }
    float* out = (float*)d_out;
    ska_kernel<<<GRIDX, NTHR>>>(x, w, out);   // 1480 full + 224 tail CTAs
}

// round 14
// speedup vs baseline: 1.1387x; 1.0050x over previous
#include <cuda_runtime.h>
#include <cstdint>

// SKA: out[n, g*8+c, h, w] = sum_{7x7} x_pad[n, g*8+c, h+i, w+j] * w[n, c, i*7+j, h, w]
// x [8,512,96,96] f32, w [8,8,49,96,96] f32, out [8,512,96,96] f32.
//
// R14 = R13 winner (cooperative lane-pair quad; 49 weight pairs = 98 regs per
// thread; 64 B LDS per output; scalar odd taps; shfl.bfly(1) merge; PITCH=112;
// 2 buffers x 4-channel slabs, barrier per 4 channels; tail-only g-split:
// 1480 full CTAs = 5 x 296 slots + 56 tail tiles split 4-way) + ILP round:
//  1. Affine staging addressing: NTHR=192=2*96 means each thread stages one
//     fixed column at rows r0s+2k -> soff[5] collapses to base + k*896B and
//     gsz[5] to a 5-bit mask. Frees ~8 registers (ptxas was at 168/170 -- no
//     headroom to hoist loads; freed regs become scheduling room).
//  2. Split accumulator chains eO->eOa/eOb, eX->eXa/eXb (max dependent chain
//     64 -> 32 cyc), spending 4 of the freed registers on ILP.

#define N_    8
#define IC    512
#define H_    96
#define W_    96
#define WC    8
#define G_    64
#define PAD   3
#define HT    4                     // output rows per CTA (2 row-groups x 2)
#define NTHR  192
#define TROWS (HT + 2 * PAD)        // 10 staged rows
#define PITCH 112                   // 3 zero | 96 data | zeros; 112%32==16
#define TILE_F (TROWS * PITCH)      // 1120 floats per channel slab
#define HW    (H_ * W_)             // 9216
#define CSTR  ((size_t)WC * HW)     // x/out channel stride between g steps
#define CPB   4                     // channels per pipeline block
#define ELPT  ((TROWS * W_) / NTHR) // 5 staged elements per thread per channel

#define NTILE 1536                  // 24 ht x 8 c x 8 n
#define FULLT 1480                  // full-64g tiles (= 5 * 296 slots exactly)
#define SPLITK 4                    // tail tiles split into 4 CTAs x 16 g
#define GRIDX (FULLT + (NTILE - FULLT) * SPLITK)   // 1480 + 224 = 1704

typedef unsigned long long u64;

static __device__ __forceinline__ void ffma2(u64& d, u64 a, u64 b) {
    asm("fma.rn.f32x2 %0, %1, %2, %0;" : "+l"(d) : "l"(a), "l"(b));
}
static __device__ __forceinline__ u64 fadd2(u64 a, u64 b) {
    u64 d; asm("add.rn.f32x2 %0, %1, %2;" : "=l"(d) : "l"(a), "l"(b)); return d;
}
// lo += xl*w.lo, hi += xh*w.hi; splitting the weight pair is register aliasing.
static __device__ __forceinline__ void odd_tap(float& lo, float& hi,
                                               float xl, float xh, u64 w) {
    asm("{\n\t"
        ".reg .f32 wl, wh;\n\t"
        "mov.b64 {wl, wh}, %4;\n\t"
        "fma.rn.f32 %0, %2, wl, %0;\n\t"
        "fma.rn.f32 %1, %3, wh, %1;\n\t"
        "}" : "+f"(lo), "+f"(hi) : "f"(xl), "f"(xh), "l"(w));
}
static __device__ __forceinline__ void unpack2(u64 v, float& a, float& b) {
    asm("mov.b64 {%0, %1}, %2;" : "=f"(a), "=f"(b) : "l"(v));
}
static __device__ __forceinline__ u64 pack2(float a, float b) {
    u64 r; asm("mov.b64 %0, {%1, %2};" : "=l"(r) : "f"(a), "f"(b)); return r;
}
static __device__ __forceinline__ u64 shfl_x1(u64 v) {
    uint32_t lo = (uint32_t)v, hi = (uint32_t)(v >> 32);
    lo = __shfl_xor_sync(0xffffffffu, lo, 1);
    hi = __shfl_xor_sync(0xffffffffu, hi, 1);
    return ((u64)hi << 32) | lo;
}
static __device__ __forceinline__ void cp4(uint32_t s, const float* g, int sz) {
    asm volatile("cp.async.ca.shared.global [%0], [%1], 4, %2;"
                 :: "r"(s), "l"(g), "r"(sz));
}

// 7 taps of one kernel row into one chain set (even pairs + odd scalars).
#define TAP7(E, LO, HI, WA)                          \
    do {                                             \
        ffma2(E, U0, (WA)[0]);                       \
        ffma2(E, U1, (WA)[2]);                       \
        ffma2(E, U2, (WA)[4]);                       \
        ffma2(E, U3, (WA)[6]);                       \
        odd_tap(LO, HI, f1, f2, (WA)[1]);            \
        odd_tap(LO, HI, f3, f4, (WA)[3]);            \
        odd_tap(LO, HI, f5, f6, (WA)[5]);            \
    } while (0)

#define LOADROW(ptr)                                 \
    const u64* rp = (const u64*)(ptr);               \
    u64 U0 = rp[0], U1 = rp[1], U2 = rp[2], U3 = rp[3];  \
    float f0, f1, f2, f3, f4, f5, f6, f7;            \
    unpack2(U0, f0, f1); unpack2(U1, f2, f3);        \
    unpack2(U2, f4, f5); unpack2(U3, f6, f7)

__global__ __launch_bounds__(NTHR, 2)
void ska_kernel(const float* __restrict__ x, const float* __restrict__ wgt,
                float* __restrict__ out) {
    __shared__ float smem[8 * TILE_F];   // 2 buffers x 4 channel slabs = 35.8 KB

    const int tid  = threadIdx.x;
    // ---- Tail-split schedule decode (uniform across the CTA) ----
    int tile, g0, nblk;
    {
        int bid = blockIdx.x;
        if (bid < FULLT) { tile = bid;                 g0 = 0;  nblk = G_ / CPB; }
        else {
            int r = bid - FULLT;                       // 0..223
            tile = FULLT + (r >> 2);                   // 4 consecutive bids/tile
            g0   = (r & 3) * (G_ / SPLITK);            // 0,16,32,48
            nblk = (G_ / SPLITK) / CPB;                // 4
        }
    }
    const int ht   = tile % 24;
    const int c    = (tile / 24) % WC;
    const int n    = tile / (24 * WC);
    const int h0   = ht * HT;
    const int role = tid & 1;            // 0 = A (rows 0..3), 1 = B (rows 7..4)
    const int pid  = tid >> 1;           // 0..95
    const int rg   = pid / 48;           // row-group: output rows 2rg, 2rg+1
    const int cp   = pid % 48;
    const int w0   = 2 * cp;

    // Zero left/right halo columns of all 8 slabs (reads touch floats 0..101).
    for (int z = tid; z < 8 * TROWS * 8; z += NTHR) {
        int b = z / (TROWS * 8), rem = z % (TROWS * 8);
        int row = rem / 8, ci = rem % 8;
        int col = (ci < 3) ? ci : 99 + (ci - 3);
        smem[b * TILE_F + row * PITCH + col] = 0.0f;
    }

    // Weight register cache: exactly 49 pairs per thread (98 regs).
    // own = pixel this role stores (A: row 2rg; B: row 2rg+1).
    // A: light = own i=0;  heavy m=0..2: own i=m+1, other i=m.
    // B: light = own i=6;  heavy m=0..2: own i=5-m, other i=6-m.
    const float* W0b = wgt + ((size_t)(n * WC + c) * 49) * HW
                           + (size_t)(h0 + 2 * rg) * W_ + w0;
    const float* ownB = role ? (W0b + W_) : W0b;
    const float* othB = role ? W0b : (W0b + W_);
    u64 WL[7], WHo[3][7], WHx[3][7];
    {
        const int liRow = role ? 6 : 0;
        #pragma unroll
        for (int j = 0; j < 7; j++)
            WL[j] = *(const u64*)(ownB + (size_t)(liRow * 7 + j) * HW);
        #pragma unroll
        for (int m = 0; m < 3; m++) {
            const int ro = role ? (5 - m) : (m + 1);
            const int rx = role ? (6 - m) : m;
            #pragma unroll
            for (int j = 0; j < 7; j++) {
                WHo[m][j] = *(const u64*)(ownB + (size_t)(ro * 7 + j) * HW);
                WHx[m][j] = *(const u64*)(othB + (size_t)(rx * 7 + j) * HW);
            }
        }
    }

    // Affine staging: thread stages column colS of rows r0s, r0s+2, ..., r0s+8.
    // (192 threads = 2 x 96 cols; row step 2 -> smem stride 2*PITCH*4 = 896 B.)
    const int r0s  = tid / W_;           // 0 or 1
    const int colS = tid - r0s * W_;     // 0..95
    const float* xc = x + (size_t)n * IC * HW + (size_t)c * HW
                        + (size_t)g0 * CSTR;     // first channel of this CTA
    const uint32_t sbase = (uint32_t)__cvta_generic_to_shared(smem)
                         + (uint32_t)(r0s * PITCH + 3 + colS) * 4u;
    int      gofs[ELPT];   // float offset within a channel (row-clamped)
    unsigned vmask = 0;    // bit k: row r0s+2k in-bounds (copy 4B) else ZFILL
    #pragma unroll
    for (int k = 0; k < ELPT; k++) {
        int row = r0s + 2 * k;
        int hr  = h0 - PAD + row;
        if (hr >= 0 && hr < H_) vmask |= 1u << k;
        int hrc = hr < 0 ? 0 : (hr >= H_ ? H_ - 1 : hr);
        gofs[k] = hrc * W_ + colS;
    }
    // Stage block b = local channels 4b..4b+3 into buffer b&1; one commit group.
    auto stage = [&](int b) {
        #pragma unroll
        for (int cc = 0; cc < CPB; cc++) {
            uint32_t sb = sbase + (uint32_t)(((b & 1) * CPB + cc) * TILE_F) * 4u;
            const float* base = xc + (size_t)(CPB * b + cc) * CSTR;
            #pragma unroll
            for (int k = 0; k < ELPT; k++)
                cp4(sb + (uint32_t)(k * 2 * PITCH * 4), base + gofs[k],
                    (int)(((vmask >> k) & 1u) << 2));
        }
        asm volatile("cp.async.commit_group;");
    };

    stage(0);

    // Per-thread tile-row float offsets: A row kk, B row 7-kk (plus row-group).
    int rowF[4];
    #pragma unroll
    for (int kk = 0; kk < 4; kk++)
        rowF[kk] = (2 * rg + (role ? (7 - kk) : kk)) * PITCH + w0;

    float* op = out + (size_t)n * IC * HW + (size_t)c * HW
                    + (size_t)g0 * CSTR
                    + (size_t)(h0 + 2 * rg + role) * W_ + w0;

    for (int b = 0; b < nblk; ++b) {
        // Block b's group was issued one full compute block ago (except b=0):
        // wait_group 0 is cheap. Barrier publishes all slab writes AND proves
        // everyone finished computing block b-1, so buffer (b+1)&1 = (b-1)&1
        // is safe to overwrite below.
        asm volatile("cp.async.wait_group 0;");
        __syncthreads();
        if (b + 1 < nblk) stage(b + 1);

        const float* bufB = smem + (b & 1) * CPB * TILE_F;
        #pragma unroll
        for (int gg = 0; gg < CPB; gg++) {
            const float* tb = bufB + gg * TILE_F;
            // Split even-tap chains (8+8 / 8+4) to halve dependency depth.
            u64 eOa = 0ull, eOb = 0ull, eXa = 0ull, eXb = 0ull;
            float oLo = 0.f, oHi = 0.f, xLo = 0.f, xHi = 0.f;  // odd scalars
            {   // light row (kk=0): own pixel only -> chain a
                LOADROW(tb + rowF[0]);
                TAP7(eOa, oLo, oHi, WL);
            }
            {   // kk=1: own -> chain b, other -> chain a
                LOADROW(tb + rowF[1]);
                TAP7(eOb, oLo, oHi, WHo[0]);
                TAP7(eXa, xLo, xHi, WHx[0]);
            }
            {   // kk=2: own -> chain a, other -> chain b
                LOADROW(tb + rowF[2]);
                TAP7(eOa, oLo, oHi, WHo[1]);
                TAP7(eXb, xLo, xHi, WHx[1]);
            }
            {   // kk=3: own -> chain b, other -> chain a
                LOADROW(tb + rowF[3]);
                TAP7(eOb, oLo, oHi, WHo[2]);
                TAP7(eXa, xLo, xHi, WHx[2]);
            }
            // Fold, swap the other-pixel partial with the partner lane, store.
            u64 ownF = fadd2(fadd2(eOa, eOb), pack2(oLo, oHi));
            u64 othF = fadd2(fadd2(eXa, eXb), pack2(xLo, xHi));
            u64 recv = shfl_x1(othF);   // partner's partial for MY pixel
            *(u64*)op = fadd2(ownF, recv);
            op += CSTR;
        }
    }
}

extern "C" void kernel_launch(void* const* d_in, const int* in_sizes, int n_in,
                              void* d_out, int out_size) {
    const float* x = (const float*)d_in[0];
    const float* w = (const float*)d_in[1];
    // x (37,748,736 elems) > w (28,901,376); guard against input ordering.
    if (n_in >= 2 && in_sizes[0] < in_sizes[1]) {
        const float* t = x; x = w; w = t;
    }
    float* out = (float*)d_out;
    ska_kernel<<<GRIDX, NTHR>>>(x, w, out);   // 1480 full + 224 tail CTAs
}